// round 7
// baseline (speedup 1.0000x reference)
#include <cuda_runtime.h>
#include <cstdint>

// ----------------------------------------------------------------------------
// Phase 1: h = inputs @ weight   (M x 256) @ (256 x 128) -> (M x 128), fp32
// Register-tiled SGEMM: BM=128, BN=128, BK=16, 256 threads, 8x8 per thread
// ----------------------------------------------------------------------------
#define BM 128
#define BN 128
#define BK 16
#define TM 8
#define TN 8

__global__ __launch_bounds__(256, 2)
void gemm_kernel(const float* __restrict__ A,   // [M, 256]
                 const float* __restrict__ B,   // [256, 128]
                 float* __restrict__ C,         // [M, 128]
                 int M) {
    __shared__ float As[BK][BM + 4];   // padded to avoid bank conflicts
    __shared__ float Bs[BK][BN];

    const int block_row = blockIdx.x * BM;
    const int tid = threadIdx.x;         // 0..255
    const int tx  = tid & 15;            // col group (16)
    const int ty  = tid >> 4;            // row group (16)

    float acc[TM][TN];
    #pragma unroll
    for (int i = 0; i < TM; i++)
        #pragma unroll
        for (int j = 0; j < TN; j++)
            acc[i][j] = 0.0f;

    for (int k0 = 0; k0 < 256; k0 += BK) {
        // Cooperative loads: A tile 128x16 (512 float4), B tile 16x128 (512 float4)
        #pragma unroll
        for (int i = 0; i < 2; i++) {
            int f = tid + i * 256;
            // A: float4 f -> row = f/4, col4 = (f%4)*4 ; store transposed
            int arow = f >> 2;
            int acol = (f & 3) << 2;
            int grow = block_row + arow;
            if (grow >= M) grow = M - 1;          // clamp (stores are guarded)
            float4 va = *(const float4*)(A + (size_t)grow * 256 + k0 + acol);
            As[acol + 0][arow] = va.x;
            As[acol + 1][arow] = va.y;
            As[acol + 2][arow] = va.z;
            As[acol + 3][arow] = va.w;
            // B: float4 f -> row = f/32, col4 = (f%32)*4
            int brow = f >> 5;
            int bcol = (f & 31) << 2;
            *(float4*)&Bs[brow][bcol] =
                *(const float4*)(B + (size_t)(k0 + brow) * 128 + bcol);
        }
        __syncthreads();

        #pragma unroll
        for (int k = 0; k < BK; k++) {
            float ra[TM], rb[TN];
            #pragma unroll
            for (int i = 0; i < TM; i++) ra[i] = As[k][ty * TM + i];
            #pragma unroll
            for (int j = 0; j < TN; j++) rb[j] = Bs[k][tx * TN + j];
            #pragma unroll
            for (int i = 0; i < TM; i++)
                #pragma unroll
                for (int j = 0; j < TN; j++)
                    acc[i][j] = fmaf(ra[i], rb[j], acc[i][j]);
        }
        __syncthreads();
    }

    // Store 8x8 per thread as float4s
    #pragma unroll
    for (int i = 0; i < TM; i++) {
        int grow = block_row + ty * TM + i;
        if (grow < M) {
            #pragma unroll
            for (int j = 0; j < TN; j += 4) {
                float4 v = make_float4(acc[i][j], acc[i][j + 1],
                                       acc[i][j + 2], acc[i][j + 3]);
                *(float4*)(C + (size_t)grow * 128 + tx * TN + j) = v;
            }
        }
    }
}

// ----------------------------------------------------------------------------
// Phase 2: edge_weight[e] = relu( sum_k |h[u,k]-h[v,k]| * a[k] )
// One warp per edge; lane l handles floats [4l, 4l+4) of the 128-dim row.
// h rows are 512B -> one coalesced float4 burst per row per warp; h fits in L2.
// NOTE: edge indices are int32 on device (JAX x64 disabled downcasts int64).
// ----------------------------------------------------------------------------
__global__ __launch_bounds__(256)
void edge_kernel(const float* __restrict__ h,    // [M, 128]
                 const int* __restrict__ edge,   // [2, E] int32
                 const float* __restrict__ a,    // [128]
                 float* __restrict__ ew,         // [E]
                 int E) {
    int gwarp = (blockIdx.x * blockDim.x + threadIdx.x) >> 5;
    int lane  = threadIdx.x & 31;
    if (gwarp >= E) return;

    int u = __ldg(edge + gwarp);
    int v = __ldg(edge + (size_t)E + gwarp);

    float4 hu = *(const float4*)(h + (size_t)u * 128 + lane * 4);
    float4 hv = *(const float4*)(h + (size_t)v * 128 + lane * 4);
    float4 av = *(const float4*)(a + lane * 4);

    float s = fabsf(hu.x - hv.x) * av.x
            + fabsf(hu.y - hv.y) * av.y
            + fabsf(hu.z - hv.z) * av.z
            + fabsf(hu.w - hv.w) * av.w;

    #pragma unroll
    for (int o = 16; o > 0; o >>= 1)
        s += __shfl_xor_sync(0xFFFFFFFFu, s, o);

    if (lane == 0) ew[gwarp] = fmaxf(s, 0.0f);
}

// ----------------------------------------------------------------------------
// Launch
// Inputs (metadata order): inputs f32 [100000,256], edge int32 [2,E],
//                          weight f32 [256,128], a f32 [128,1]
// Output: concat( h [M*128], edge_weight [E] ) fp32
// ----------------------------------------------------------------------------
extern "C" void kernel_launch(void* const* d_in, const int* in_sizes, int n_in,
                              void* d_out, int out_size) {
    const float* inputs = (const float*)d_in[0];
    const int*   edge   = (const int*)d_in[1];
    const float* weight = (const float*)d_in[2];
    const float* a      = (const float*)d_in[3];

    const int M = in_sizes[0] / 256;
    const int E = in_sizes[1] / 2;

    float* h  = (float*)d_out;
    float* ew = (float*)d_out + (size_t)M * 128;

    // Phase 1: GEMM
    int gemm_blocks = (M + BM - 1) / BM;
    gemm_kernel<<<gemm_blocks, 256>>>(inputs, weight, h, M);

    // Phase 2: edge attention (depends on h; same stream => ordered)
    int warps_per_block = 256 / 32;
    int edge_blocks = (E + warps_per_block - 1) / warps_per_block;
    edge_kernel<<<edge_blocks, 256>>>(h, edge, a, ew, E);
}

// round 9
// speedup vs baseline: 1.0350x; 1.0350x over previous
#include <cuda_runtime.h>
#include <cstdint>

// ----------------------------------------------------------------------------
// Phase 1: h = inputs @ weight   (M x 256) @ (256 x 128) -> (M x 128), fp32
// Register-tiled SGEMM, double-buffered SMEM: BM=128, BN=128, BK=16,
// 256 threads, 8x8 per thread, 1 __syncthreads per K-step.
// ----------------------------------------------------------------------------
#define BM 128
#define BN 128
#define BK 16
#define TM 8
#define TN 8
#define NSTEPS (256 / BK)

__global__ __launch_bounds__(256, 2)
void gemm_kernel(const float* __restrict__ A,   // [M, 256]
                 const float* __restrict__ B,   // [256, 128]
                 float* __restrict__ C,         // [M, 128]
                 int M) {
    __shared__ float As[2][BK][BM + 4];
    __shared__ float Bs[2][BK][BN];

    const int block_row = blockIdx.x * BM;
    const int tid = threadIdx.x;         // 0..255
    const int tx  = tid & 15;            // col group (16)
    const int ty  = tid >> 4;            // row group (16)

    // cooperative-load coordinates (2 float4 per thread per tile per matrix)
    const int arow0 = tid >> 2;                 // f = tid
    const int acol0 = (tid & 3) << 2;
    const int arow1 = (tid + 256) >> 2;         // f = tid + 256
    const int acol1 = ((tid + 256) & 3) << 2;
    const int brow0 = tid >> 5;
    const int bcol0 = (tid & 31) << 2;
    const int brow1 = (tid + 256) >> 5;
    const int bcol1 = bcol0;

    int gr0 = block_row + arow0; if (gr0 >= M) gr0 = M - 1;
    int gr1 = block_row + arow1; if (gr1 >= M) gr1 = M - 1;

    float acc[TM][TN];
    #pragma unroll
    for (int i = 0; i < TM; i++)
        #pragma unroll
        for (int j = 0; j < TN; j++)
            acc[i][j] = 0.0f;

    // preload tile 0 into buffer 0
    {
        float4 va0 = *(const float4*)(A + (size_t)gr0 * 256 + acol0);
        float4 va1 = *(const float4*)(A + (size_t)gr1 * 256 + acol1);
        float4 vb0 = *(const float4*)(B + (size_t)brow0 * 128 + bcol0);
        float4 vb1 = *(const float4*)(B + (size_t)brow1 * 128 + bcol1);
        As[0][acol0 + 0][arow0] = va0.x; As[0][acol0 + 1][arow0] = va0.y;
        As[0][acol0 + 2][arow0] = va0.z; As[0][acol0 + 3][arow0] = va0.w;
        As[0][acol1 + 0][arow1] = va1.x; As[0][acol1 + 1][arow1] = va1.y;
        As[0][acol1 + 2][arow1] = va1.z; As[0][acol1 + 3][arow1] = va1.w;
        *(float4*)&Bs[0][brow0][bcol0] = vb0;
        *(float4*)&Bs[0][brow1][bcol1] = vb1;
    }
    __syncthreads();

    #pragma unroll
    for (int t = 0; t < NSTEPS; t++) {
        const int cur = t & 1;
        const int nxt = cur ^ 1;
        float4 va0, va1, vb0, vb1;
        const bool has_next = (t + 1 < NSTEPS);
        if (has_next) {
            const int k0 = (t + 1) * BK;
            va0 = *(const float4*)(A + (size_t)gr0 * 256 + k0 + acol0);
            va1 = *(const float4*)(A + (size_t)gr1 * 256 + k0 + acol1);
            vb0 = *(const float4*)(B + (size_t)(k0 + brow0) * 128 + bcol0);
            vb1 = *(const float4*)(B + (size_t)(k0 + brow1) * 128 + bcol1);
        }

        #pragma unroll
        for (int k = 0; k < BK; k++) {
            float ra[TM], rb[TN];
            #pragma unroll
            for (int i = 0; i < TM; i++) ra[i] = As[cur][k][ty * TM + i];
            #pragma unroll
            for (int j = 0; j < TN; j++) rb[j] = Bs[cur][k][tx * TN + j];
            #pragma unroll
            for (int i = 0; i < TM; i++)
                #pragma unroll
                for (int j = 0; j < TN; j++)
                    acc[i][j] = fmaf(ra[i], rb[j], acc[i][j]);
        }

        if (has_next) {
            As[nxt][acol0 + 0][arow0] = va0.x; As[nxt][acol0 + 1][arow0] = va0.y;
            As[nxt][acol0 + 2][arow0] = va0.z; As[nxt][acol0 + 3][arow0] = va0.w;
            As[nxt][acol1 + 0][arow1] = va1.x; As[nxt][acol1 + 1][arow1] = va1.y;
            As[nxt][acol1 + 2][arow1] = va1.z; As[nxt][acol1 + 3][arow1] = va1.w;
            *(float4*)&Bs[nxt][brow0][bcol0] = vb0;
            *(float4*)&Bs[nxt][brow1][bcol1] = vb1;
            __syncthreads();
        }
    }

    // Store 8x8 per thread as float4s
    #pragma unroll
    for (int i = 0; i < TM; i++) {
        int grow = block_row + ty * TM + i;
        if (grow < M) {
            #pragma unroll
            for (int j = 0; j < TN; j += 4) {
                float4 v = make_float4(acc[i][j], acc[i][j + 1],
                                       acc[i][j + 2], acc[i][j + 3]);
                *(float4*)(C + (size_t)grow * 128 + tx * TN + j) = v;
            }
        }
    }
}

// ----------------------------------------------------------------------------
// Phase 2: edge_weight[e] = relu( sum_k |h[u,k]-h[v,k]| * a[k] )
// FOUR edges per warp: two int4 broadcast index loads, then 8 independent
// 512B row gathers in flight (MLP=8). __ldcg bypasses L1 (h is L2-resident,
// zero L1 reuse). Butterfly-reduce all 4 sums; lanes 0-3 write.
// ----------------------------------------------------------------------------
__global__ __launch_bounds__(256)
void edge_kernel(const float* __restrict__ h,    // [M, 128]
                 const int* __restrict__ edge,   // [2, E] int32
                 const float* __restrict__ a,    // [128]
                 float* __restrict__ ew,         // [E]
                 int E) {
    const int warp = (blockIdx.x * blockDim.x + threadIdx.x) >> 5;
    const int lane = threadIdx.x & 31;
    const int e0 = warp * 4;
    if (e0 >= E) return;

    const float4 av = __ldg((const float4*)(a) + lane);

    // E is a multiple of 4 here; int4 loads are in-bounds and 16B-aligned.
    const int4 uu = __ldg((const int4*)(edge) + warp);
    const int4 vv = __ldg((const int4*)(edge + (size_t)E) + warp);
    const int u[4] = {uu.x, uu.y, uu.z, uu.w};
    const int v[4] = {vv.x, vv.y, vv.z, vv.w};

    // Issue all 8 gathers before consuming any
    float4 hu[4], hv[4];
    #pragma unroll
    for (int i = 0; i < 4; i++)
        hu[i] = __ldcg((const float4*)(h + (size_t)u[i] * 128) + lane);
    #pragma unroll
    for (int i = 0; i < 4; i++)
        hv[i] = __ldcg((const float4*)(h + (size_t)v[i] * 128) + lane);

    float s[4];
    #pragma unroll
    for (int i = 0; i < 4; i++) {
        s[i] = fabsf(hu[i].x - hv[i].x) * av.x
             + fabsf(hu[i].y - hv[i].y) * av.y
             + fabsf(hu[i].z - hv[i].z) * av.z
             + fabsf(hu[i].w - hv[i].w) * av.w;
    }

    #pragma unroll
    for (int o = 16; o > 0; o >>= 1) {
        #pragma unroll
        for (int i = 0; i < 4; i++)
            s[i] += __shfl_xor_sync(0xFFFFFFFFu, s[i], o);
    }

    if (lane < 4) {
        int e = e0 + lane;
        if (e < E) ew[e] = fmaxf(s[lane], 0.0f);
    }
}

// ----------------------------------------------------------------------------
// Launch
// Inputs (metadata order): inputs f32 [100000,256], edge int32 [2,E],
//                          weight f32 [256,128], a f32 [128,1]
// Output: concat( h [M*128], edge_weight [E] ) fp32
// ----------------------------------------------------------------------------
extern "C" void kernel_launch(void* const* d_in, const int* in_sizes, int n_in,
                              void* d_out, int out_size) {
    const float* inputs = (const float*)d_in[0];
    const int*   edge   = (const int*)d_in[1];
    const float* weight = (const float*)d_in[2];
    const float* a      = (const float*)d_in[3];

    const int M = in_sizes[0] / 256;
    const int E = in_sizes[1] / 2;

    float* h  = (float*)d_out;
    float* ew = (float*)d_out + (size_t)M * 128;

    int gemm_blocks = (M + BM - 1) / BM;
    gemm_kernel<<<gemm_blocks, 256>>>(inputs, weight, h, M);

    // 4 edges per warp, 8 warps per block => 32 edges per block
    int edge_blocks = (E + 31) / 32;
    edge_kernel<<<edge_blocks, 256>>>(h, edge, a, ew, E);
}

// round 12
// speedup vs baseline: 1.8262x; 1.7646x over previous
#include <cuda_runtime.h>
#include <cuda_bf16.h>
#include <cstdint>

// ============================================================================
// Baseline-PTX tensor-core helpers (sm_80+; compiles for plain sm_103 target)
// ============================================================================
__device__ __forceinline__ uint32_t smem_u32(const void* p) {
    uint32_t a;
    asm("{ .reg .u64 t; cvta.to.shared.u64 t, %1; cvt.u32.u64 %0, t; }"
        : "=r"(a) : "l"(p));
    return a;
}
__device__ __forceinline__ void ldsm_x4(uint32_t (&r)[4], uint32_t addr) {
    asm volatile("ldmatrix.sync.aligned.m8n8.x4.shared.b16 {%0,%1,%2,%3}, [%4];"
                 : "=r"(r[0]), "=r"(r[1]), "=r"(r[2]), "=r"(r[3]) : "r"(addr));
}
__device__ __forceinline__ void ldsm_x2(uint32_t (&r)[2], uint32_t addr) {
    asm volatile("ldmatrix.sync.aligned.m8n8.x2.shared.b16 {%0,%1}, [%2];"
                 : "=r"(r[0]), "=r"(r[1]) : "r"(addr));
}
__device__ __forceinline__ void mma_bf16(float (&d)[4], const uint32_t (&a)[4],
                                         const uint32_t (&b)[2]) {
    asm volatile(
        "mma.sync.aligned.m16n8k16.row.col.f32.bf16.bf16.f32 "
        "{%0,%1,%2,%3}, {%4,%5,%6,%7}, {%8,%9}, {%0,%1,%2,%3};"
        : "+f"(d[0]), "+f"(d[1]), "+f"(d[2]), "+f"(d[3])
        : "r"(a[0]), "r"(a[1]), "r"(a[2]), "r"(a[3]), "r"(b[0]), "r"(b[1]));
}
__device__ __forceinline__ uint32_t pack_bf16(__nv_bfloat16 a, __nv_bfloat16 b) {
    uint32_t lo = (uint32_t)__bfloat16_as_ushort(a);
    uint32_t hi = (uint32_t)__bfloat16_as_ushort(b);
    return (hi << 16) | lo;
}

// ============================================================================
// Wt hi/lo split, transposed to [n][k] (B col-major for row.col mma)
// ============================================================================
__device__ __nv_bfloat16 g_wt_hi[128 * 256];
__device__ __nv_bfloat16 g_wt_lo[128 * 256];

__global__ void prep_kernel(const float* __restrict__ W) {   // W [256 k][128 n]
    int idx = blockIdx.x * blockDim.x + threadIdx.x;         // 0..32767
    if (idx >= 256 * 128) return;
    int k = idx >> 7;
    int n = idx & 127;
    float w = W[idx];
    __nv_bfloat16 hi = __float2bfloat16(w);
    __nv_bfloat16 lo = __float2bfloat16(w - __bfloat162float(hi));
    g_wt_hi[n * 256 + k] = hi;
    g_wt_lo[n * 256 + k] = lo;
}

// ============================================================================
// Phase 1: h = inputs @ W, mma.sync bf16 two-term split (HH + HL + LH), fp32 acc
// CTA: 128 rows x 128 cols, K=256 in 4 chunks of 64. 8 warps (4m x 2n),
// warp tile 32x64 = 2 x 8 m16n8k16 fragments.
// ============================================================================
#define LDT 72            // smem row stride in bf16 (64 + 8 pad: LDSM conflict-free)
static constexpr int SM_AHI = 0;
static constexpr int SM_ALO = SM_AHI + 128 * LDT * 2;   // 18432
static constexpr int SM_BHI = SM_ALO + 128 * LDT * 2;
static constexpr int SM_BLO = SM_BHI + 128 * LDT * 2;
static constexpr int SM_TOTAL = SM_BLO + 128 * LDT * 2; // 73728

__global__ __launch_bounds__(256)
void gemm_mma_kernel(const float* __restrict__ A,   // [M, 256]
                     float* __restrict__ C,         // [M, 128]
                     int M) {
    extern __shared__ char smem[];
    const uint32_t sb = smem_u32(smem);
    const int tid = threadIdx.x;
    const int wid = tid >> 5;
    const int lane = tid & 31;
    const int block_row = blockIdx.x * 128;

    const int warp_m = wid & 3;          // 0..3 -> 32-row slab
    const int warp_n = wid >> 2;         // 0..1 -> 64-col slab

    float acc[2][8][4];
    #pragma unroll
    for (int mt = 0; mt < 2; mt++)
        #pragma unroll
        for (int nt = 0; nt < 8; nt++)
            #pragma unroll
            for (int j = 0; j < 4; j++)
                acc[mt][nt][j] = 0.0f;

    const uint32_t* wh32 = (const uint32_t*)g_wt_hi;
    const uint32_t* wl32 = (const uint32_t*)g_wt_lo;

    // ldmatrix per-lane addresses (byte offsets into smem), fixed per warp
    // A x4: row = mbase + (lane&15), col = k0 + ((lane>>4)<<3)
    const int a_r = (lane & 15);
    const int a_c = ((lane >> 4) << 3);
    // B x2: row = nbase + (lane&7), col = k0 + (((lane>>3)&1)<<3)
    const int b_r = (lane & 7) + ((lane & 16) ? 0 : 0);   // lanes 16-31 mirror 0-15
    const int b_c = (((lane >> 3) & 1) << 3);

    #pragma unroll 1
    for (int c = 0; c < 4; c++) {
        if (c > 0) __syncthreads();      // smem reuse: previous mma must be done

        // ---- stage A chunk: fp32 -> bf16 hi/lo into smem ----
        #pragma unroll
        for (int i = 0; i < 16; i++) {
            int p = tid + 256 * i;            // pair index 0..4095
            int r = p >> 5;                   // row 0..127
            int c2 = (p & 31) << 1;           // even k-col 0..62
            int grow = block_row + r;
            if (grow >= M) grow = M - 1;
            float2 v = *(const float2*)(A + (size_t)grow * 256 + c * 64 + c2);
            __nv_bfloat16 h0 = __float2bfloat16(v.x);
            __nv_bfloat16 h1 = __float2bfloat16(v.y);
            __nv_bfloat16 l0 = __float2bfloat16(v.x - __bfloat162float(h0));
            __nv_bfloat16 l1 = __float2bfloat16(v.y - __bfloat162float(h1));
            uint32_t off = (uint32_t)(r * LDT + c2) * 2;
            *(uint32_t*)(smem + SM_AHI + off) = pack_bf16(h0, h1);
            *(uint32_t*)(smem + SM_ALO + off) = pack_bf16(l0, l1);
        }
        // ---- stage B chunk: copy Wt hi/lo (bf16, [n][k]) into padded smem ----
        #pragma unroll
        for (int i = 0; i < 16; i++) {
            int p = tid + 256 * i;
            int n = p >> 5;                   // n row 0..127
            int kk = p & 31;                  // uint32 (bf16 pair) index in chunk
            int gidx = n * 128 + c * 32 + kk;
            uint32_t off = (uint32_t)(n * LDT + (kk << 1)) * 2;
            *(uint32_t*)(smem + SM_BHI + off) = wh32[gidx];
            *(uint32_t*)(smem + SM_BLO + off) = wl32[gidx];
        }
        __syncthreads();

        // ---- mma over 4 K-steps of 16 ----
        #pragma unroll
        for (int s = 0; s < 4; s++) {
            const int k0 = s * 16;
            uint32_t ah[2][4], al[2][4];
            #pragma unroll
            for (int mt = 0; mt < 2; mt++) {
                int row = warp_m * 32 + mt * 16 + a_r;
                uint32_t off = (uint32_t)(row * LDT + k0 + a_c) * 2;
                ldsm_x4(ah[mt], sb + SM_AHI + off);
                ldsm_x4(al[mt], sb + SM_ALO + off);
            }
            #pragma unroll
            for (int nt = 0; nt < 8; nt++) {
                int nrow = warp_n * 64 + nt * 8 + b_r;
                uint32_t off = (uint32_t)(nrow * LDT + k0 + b_c) * 2;
                uint32_t bh[2], bl[2];
                ldsm_x2(bh, sb + SM_BHI + off);
                ldsm_x2(bl, sb + SM_BLO + off);
                #pragma unroll
                for (int mt = 0; mt < 2; mt++) {
                    mma_bf16(acc[mt][nt], ah[mt], bh);   // HH
                    mma_bf16(acc[mt][nt], ah[mt], bl);   // HL
                    mma_bf16(acc[mt][nt], al[mt], bh);   // LH
                }
            }
        }
    }

    // ---- epilogue: c-frag layout -> global fp32 stores ----
    const int rbase = block_row + warp_m * 32 + (lane >> 2);
    const int cbase = warp_n * 64 + ((lane & 3) << 1);
    #pragma unroll
    for (int mt = 0; mt < 2; mt++) {
        int r0 = rbase + mt * 16;
        int r1 = r0 + 8;
        #pragma unroll
        for (int nt = 0; nt < 8; nt++) {
            int col = cbase + nt * 8;
            if (r0 < M)
                *(float2*)(C + (size_t)r0 * 128 + col) =
                    make_float2(acc[mt][nt][0], acc[mt][nt][1]);
            if (r1 < M)
                *(float2*)(C + (size_t)r1 * 128 + col) =
                    make_float2(acc[mt][nt][2], acc[mt][nt][3]);
        }
    }
}

// ----------------------------------------------------------------------------
// Phase 2: edge_weight[e] = relu( sum_k |h[u,k]-h[v,k]| * a[k] )
// UNCHANGED from the 114.8us version: 4 edges/warp, int4 index loads,
// __ldcg gathers (h L2-resident), butterfly reduce.
// ----------------------------------------------------------------------------
__global__ __launch_bounds__(256)
void edge_kernel(const float* __restrict__ h,    // [M, 128]
                 const int* __restrict__ edge,   // [2, E] int32
                 const float* __restrict__ a,    // [128]
                 float* __restrict__ ew,         // [E]
                 int E) {
    const int warp = (blockIdx.x * blockDim.x + threadIdx.x) >> 5;
    const int lane = threadIdx.x & 31;
    const int e0 = warp * 4;
    if (e0 >= E) return;

    const float4 av = __ldg((const float4*)(a) + lane);
    const int4 uu = __ldg((const int4*)(edge) + warp);
    const int4 vv = __ldg((const int4*)(edge + (size_t)E) + warp);
    const int u[4] = {uu.x, uu.y, uu.z, uu.w};
    const int v[4] = {vv.x, vv.y, vv.z, vv.w};

    float4 hu[4], hv[4];
    #pragma unroll
    for (int i = 0; i < 4; i++)
        hu[i] = __ldcg((const float4*)(h + (size_t)u[i] * 128) + lane);
    #pragma unroll
    for (int i = 0; i < 4; i++)
        hv[i] = __ldcg((const float4*)(h + (size_t)v[i] * 128) + lane);

    float s[4];
    #pragma unroll
    for (int i = 0; i < 4; i++) {
        s[i] = fabsf(hu[i].x - hv[i].x) * av.x
             + fabsf(hu[i].y - hv[i].y) * av.y
             + fabsf(hu[i].z - hv[i].z) * av.z
             + fabsf(hu[i].w - hv[i].w) * av.w;
    }
    #pragma unroll
    for (int o = 16; o > 0; o >>= 1) {
        #pragma unroll
        for (int i = 0; i < 4; i++)
            s[i] += __shfl_xor_sync(0xFFFFFFFFu, s[i], o);
    }
    if (lane < 4) {
        int e = e0 + lane;
        if (e < E) ew[e] = fmaxf(s[lane], 0.0f);
    }
}

// ----------------------------------------------------------------------------
// Launch: prep (W -> bf16 hi/lo [n][k]) -> mma.sync GEMM -> edge kernel
// Output: concat( h [M*128], edge_weight [E] ) fp32
// ----------------------------------------------------------------------------
extern "C" void kernel_launch(void* const* d_in, const int* in_sizes, int n_in,
                              void* d_out, int out_size) {
    const float* inputs = (const float*)d_in[0];
    const int*   edge   = (const int*)d_in[1];
    const float* weight = (const float*)d_in[2];
    const float* a      = (const float*)d_in[3];

    const int M = in_sizes[0] / 256;
    const int E = in_sizes[1] / 2;

    float* h  = (float*)d_out;
    float* ew = (float*)d_out + (size_t)M * 128;

    // Unconditional (deterministic, capture-safe): opt in to 72KB dynamic smem.
    cudaFuncSetAttribute(gemm_mma_kernel,
                         cudaFuncAttributeMaxDynamicSharedMemorySize, SM_TOTAL);

    prep_kernel<<<128, 256>>>(weight);

    int gemm_blocks = (M + 127) / 128;
    gemm_mma_kernel<<<gemm_blocks, 256, SM_TOTAL>>>(inputs, h, M);

    int edge_blocks = (E + 31) / 32;
    edge_kernel<<<edge_blocks, 256>>>(h, edge, a, ew, E);
}